// round 4
// baseline (speedup 1.0000x reference)
#include <cuda_runtime.h>

// CIN_74603581932155 — per-batch GEMM formulation:
//   For each b: Z(128 x 128cols) = W(128 x K) * U(K x 128cols)
//   U[h*32+m][col] = hid[h][col] * x0[m][col],  col = b'*64 + d  (2 b per CTA)
//   K = 1024 (layer 0, hid = x0) or 4096 (layers 1,2)
//   out[b, layer*128 + o] = sum_d relu(Z + bias)
// fp32 throughput via packed fma.rn.f32x2 (FFMA2): 2x the 3-reg FFMA rate on sm_103a.

namespace {

constexpr int Bt   = 1024;
constexpr int Fd   = 32;
constexpr int Dd   = 64;
constexpr int HD   = 128;
constexpr int BT   = 2;      // batch elements per CTA
constexpr int NCOL = BT * Dd;   // 128
constexpr int KT   = 32;     // k-tile = one h row (F = 32)
constexpr int WPAD = 264;    // Ws2 row stride (floats): 256 duplicated + 8 pad
constexpr int UPAD = 132;    // Us row stride
constexpr int HPAD = 132;    // hids row stride
constexpr int THREADS = 256;
constexpr int OUTW = 3 * HD; // 384

struct Smem {
    float x0s[Fd][NCOL];    // 16384 B   x0s[m][col]
    float hids[HD][HPAD];   // 67584 B   hid[h][col] (current layer input / next output)
    float Ws2[KT][WPAD];    // 33792 B   W tile, each value duplicated: [k][2o]=[k][2o+1]=W[o][k]
    float Us[KT][UPAD];     // 16896 B   U tile [k][col]
};                          // total 134656 B

__device__ __forceinline__ unsigned long long ffma2(unsigned long long a,
                                                    unsigned long long b,
                                                    unsigned long long c) {
    unsigned long long d;
    asm("fma.rn.f32x2 %0, %1, %2, %3;" : "=l"(d) : "l"(a), "l"(b), "l"(c));
    return d;
}

__device__ __forceinline__ void unpack2(unsigned long long v, float& lo, float& hi) {
    asm("mov.b64 {%0, %1}, %2;" : "=f"(lo), "=f"(hi) : "l"(v));
}

__global__ void __launch_bounds__(THREADS, 1)
cin_kernel(const float* __restrict__ x,
           const float* __restrict__ W0, const float* __restrict__ bias0,
           const float* __restrict__ W1, const float* __restrict__ bias1,
           const float* __restrict__ W2, const float* __restrict__ bias2,
           float* __restrict__ out)
{
    extern __shared__ float smraw[];
    Smem& sm = *reinterpret_cast<Smem*>(smraw);
    const int tid = threadIdx.x;
    const int b0  = blockIdx.x * BT;

    // ---- load x0 tile: x[b0+bb][m][d] -> x0s[m][bb*64+d] ----
    {
        const float* xg = x + (size_t)b0 * Fd * Dd;
        #pragma unroll
        for (int i = 0; i < 4; ++i) {
            int idx = tid + THREADS * i;         // 0..1023 float4s
            int m  = idx >> 5;
            int r  = idx & 31;
            int bb = r >> 4;
            int d4 = r & 15;
            float4 v = *reinterpret_cast<const float4*>(xg + bb * (Fd * Dd) + m * Dd + d4 * 4);
            *reinterpret_cast<float4*>(&sm.x0s[m][bb * Dd + d4 * 4]) = v;
        }
    }

    // ---- thread role mappings ----
    // W global->smem: each thread loads 4 float4 along k for one row o (conflict-free dup STS)
    const int wo = (tid & 31) + (((tid >> 5) & 3) << 5);  // o in [0,128), 32 distinct per warp
    const int jb = (tid >> 7) * 4;                        // float4 column group base (0 or 4)
    // U generation
    const int ucol = tid & 127;
    const int umg  = tid >> 7;
    // compute: 16(o) x 16(col) threads, 8x8 output tile each
    const int to = tid >> 4;
    const int tc = tid & 15;
    // output reduction
    const int oo = tid & 127;
    const int ob = tid >> 7;

    const float* Wls[3]  = {W0, W1, W2};
    const float* bls[3]  = {bias0, bias1, bias2};
    const int    Ks[3]   = {Fd * Fd, HD * Fd, HD * Fd};

    for (int layer = 0; layer < 3; ++layer) {
        const float* Wl = Wls[layer];
        const int K  = Ks[layer];
        const int nk = K / KT;

        unsigned long long acc[8][4];
        #pragma unroll
        for (int i = 0; i < 8; ++i)
            #pragma unroll
            for (int j = 0; j < 4; ++j) acc[i][j] = 0ull;

        // prefetch W tile 0 into registers
        float4 wreg[4];
        #pragma unroll
        for (int i = 0; i < 4; ++i)
            wreg[i] = *reinterpret_cast<const float4*>(Wl + (size_t)wo * K + (jb + i) * 4);

        for (int kt = 0; kt < nk; ++kt) {
            __syncthreads();   // previous compute done reading Ws2/Us (also covers x0 load)

            // stage W tile to smem, duplicated pairs for direct f32x2 operand loads
            #pragma unroll
            for (int i = 0; i < 4; ++i) {
                int kr = (jb + i) * 4;
                float4 v = wreg[i];
                *reinterpret_cast<float2*>(&sm.Ws2[kr + 0][2 * wo]) = make_float2(v.x, v.x);
                *reinterpret_cast<float2*>(&sm.Ws2[kr + 1][2 * wo]) = make_float2(v.y, v.y);
                *reinterpret_cast<float2*>(&sm.Ws2[kr + 2][2 * wo]) = make_float2(v.z, v.z);
                *reinterpret_cast<float2*>(&sm.Ws2[kr + 3][2 * wo]) = make_float2(v.w, v.w);
            }

            // generate U tile: Us[m][col] = hsrc[kt][col] * x0s[m][col]  (h == kt)
            {
                float hv = (layer == 0) ? sm.x0s[kt][ucol] : sm.hids[kt][ucol];
                #pragma unroll
                for (int i = 0; i < 16; ++i) {
                    int m = umg * 16 + i;
                    sm.Us[m][ucol] = hv * sm.x0s[m][ucol];
                }
            }
            __syncthreads();

            // prefetch next W tile (LDG overlaps the ~4K-cycle tile compute)
            if (kt + 1 < nk) {
                const float* base = Wl + (size_t)wo * K + (size_t)(kt + 1) * KT;
                #pragma unroll
                for (int i = 0; i < 4; ++i)
                    wreg[i] = *reinterpret_cast<const float4*>(base + (jb + i) * 4);
            }

            // main FFMA2 loop: per k, 6 LDS.128 + 32 fma.f32x2
            #pragma unroll 2
            for (int k = 0; k < KT; ++k) {
                ulonglong2 a01 = *reinterpret_cast<const ulonglong2*>(&sm.Ws2[k][to * 16 + 0]);
                ulonglong2 a23 = *reinterpret_cast<const ulonglong2*>(&sm.Ws2[k][to * 16 + 4]);
                ulonglong2 a45 = *reinterpret_cast<const ulonglong2*>(&sm.Ws2[k][to * 16 + 8]);
                ulonglong2 a67 = *reinterpret_cast<const ulonglong2*>(&sm.Ws2[k][to * 16 + 12]);
                ulonglong2 c01 = *reinterpret_cast<const ulonglong2*>(&sm.Us[k][tc * 8 + 0]);
                ulonglong2 c23 = *reinterpret_cast<const ulonglong2*>(&sm.Us[k][tc * 8 + 4]);
                unsigned long long a[8] = {a01.x, a01.y, a23.x, a23.y,
                                           a45.x, a45.y, a67.x, a67.y};
                unsigned long long c[4] = {c01.x, c01.y, c23.x, c23.y};
                #pragma unroll
                for (int i = 0; i < 8; ++i)
                    #pragma unroll
                    for (int j = 0; j < 4; ++j)
                        acc[i][j] = ffma2(a[i], c[j], acc[i][j]);
            }
        }

        // ---- epilogue: bias + ReLU -> hids (safe: k-loop fully consumed old hids) ----
        {
            const float* bl = bls[layer];
            float bi[8];
            #pragma unroll
            for (int i = 0; i < 8; ++i) bi[i] = __ldg(&bl[to * 8 + i]);

            #pragma unroll
            for (int i = 0; i < 8; ++i) {
                float r[8];
                #pragma unroll
                for (int j = 0; j < 4; ++j) {
                    float lo, hi;
                    unpack2(acc[i][j], lo, hi);
                    lo += bi[i]; hi += bi[i];
                    r[2 * j]     = fmaxf(lo, 0.0f);
                    r[2 * j + 1] = fmaxf(hi, 0.0f);
                }
                *reinterpret_cast<float4*>(&sm.hids[to * 8 + i][tc * 8 + 0]) =
                    make_float4(r[0], r[1], r[2], r[3]);
                *reinterpret_cast<float4*>(&sm.hids[to * 8 + i][tc * 8 + 4]) =
                    make_float4(r[4], r[5], r[6], r[7]);
            }
        }
        __syncthreads();

        // ---- out[b0+ob, layer*128 + oo] = sum_d hids[oo][ob*64 + d] ----
        {
            float s = 0.0f;
            #pragma unroll
            for (int d4 = 0; d4 < 16; ++d4) {
                float4 v = *reinterpret_cast<const float4*>(&sm.hids[oo][ob * Dd + d4 * 4]);
                s += (v.x + v.y) + (v.z + v.w);
            }
            out[(size_t)(b0 + ob) * OUTW + layer * HD + oo] = s;
        }
        // next layer's top-of-loop __syncthreads orders this read before Ws2/Us reuse;
        // hids is only rewritten at the next epilogue, after a fully synced k-loop.
    }
}

} // namespace

extern "C" void kernel_launch(void* const* d_in, const int* in_sizes, int n_in,
                              void* d_out, int out_size) {
    const float* x  = (const float*)d_in[0];
    const float* W0 = (const float*)d_in[1];
    const float* b0 = (const float*)d_in[2];
    const float* W1 = (const float*)d_in[3];
    const float* b1 = (const float*)d_in[4];
    const float* W2 = (const float*)d_in[5];
    const float* b2 = (const float*)d_in[6];
    float* out = (float*)d_out;

    static_assert(sizeof(Smem) <= 227 * 1024, "smem budget");
    cudaFuncSetAttribute(cin_kernel, cudaFuncAttributeMaxDynamicSharedMemorySize,
                         (int)sizeof(Smem));
    cin_kernel<<<Bt / BT, THREADS, sizeof(Smem)>>>(x, W0, b0, W1, b1, W2, b2, out);
}

// round 5
// speedup vs baseline: 1.0785x; 1.0785x over previous
#include <cuda_runtime.h>

// CIN_74603581932155 — per-batch GEMM formulation:
//   For each b: Z(128 x 128cols) = W(128 x K) * U(K x 128cols)
//   U[h*32+m][col] = hid[h][col] * x0[m][col],  col = b'*64 + d  (2 b per CTA)
//   K = 1024 (layer 0, hid = x0) or 4096 (layers 1,2)
//   out[b, layer*128 + o] = sum_d relu(Z + bias)
// fp32 via packed fma.rn.f32x2 (FFMA2). R4: double-buffered Ws2/Us so the
// W-dup + U-gen staging overlaps the FFMA2 loop; 1 barrier/tile instead of 2;
// vectorized U-gen (STS.128).

namespace {

constexpr int Bt   = 1024;
constexpr int Fd   = 32;
constexpr int Dd   = 64;
constexpr int HD   = 128;
constexpr int BT   = 2;         // batch elements per CTA
constexpr int NCOL = BT * Dd;   // 128
constexpr int KT   = 32;        // k-tile = one h row (F = 32)
constexpr int WPAD = 264;       // Ws2 row stride (floats): 256 duplicated + 8 pad
constexpr int UPAD = 132;       // Us row stride
constexpr int HPAD = 132;       // hids row stride (16B-aligned rows)
constexpr int THREADS = 256;
constexpr int OUTW = 3 * HD;    // 384

struct Smem {
    float x0s[Fd][NCOL];      // 16384 B
    float hids[HD][HPAD];     // 67584 B
    float Ws2[2][KT][WPAD];   // 67584 B  double-buffered dup W tile: [k][2o]=[k][2o+1]=W[o][k]
    float Us[2][KT][UPAD];    // 33792 B  double-buffered U tile [m][col]
};                            // total 185344 B

__device__ __forceinline__ unsigned long long ffma2(unsigned long long a,
                                                    unsigned long long b,
                                                    unsigned long long c) {
    unsigned long long d;
    asm("fma.rn.f32x2 %0, %1, %2, %3;" : "=l"(d) : "l"(a), "l"(b), "l"(c));
    return d;
}

__device__ __forceinline__ void unpack2(unsigned long long v, float& lo, float& hi) {
    asm("mov.b64 {%0, %1}, %2;" : "=f"(lo), "=f"(hi) : "l"(v));
}

__global__ void __launch_bounds__(THREADS, 1)
cin_kernel(const float* __restrict__ x,
           const float* __restrict__ W0, const float* __restrict__ bias0,
           const float* __restrict__ W1, const float* __restrict__ bias1,
           const float* __restrict__ W2, const float* __restrict__ bias2,
           float* __restrict__ out)
{
    extern __shared__ float smraw[];
    Smem& sm = *reinterpret_cast<Smem*>(smraw);
    const int tid = threadIdx.x;
    const int b0  = blockIdx.x * BT;

    // ---- load x0 tile: x[b0+bb][m][d] -> x0s[m][bb*64+d] ----
    {
        const float* xg = x + (size_t)b0 * Fd * Dd;
        #pragma unroll
        for (int i = 0; i < 4; ++i) {
            int idx = tid + THREADS * i;         // 0..1023 float4s
            int m  = idx >> 5;
            int r  = idx & 31;
            int bb = r >> 4;
            int d4 = r & 15;
            float4 v = *reinterpret_cast<const float4*>(xg + bb * (Fd * Dd) + m * Dd + d4 * 4);
            *reinterpret_cast<float4*>(&sm.x0s[m][bb * Dd + d4 * 4]) = v;
        }
    }

    // ---- thread role mappings ----
    // W global->smem: thread loads 4 float4 along k for one row wo
    const int wo = (tid & 31) + (((tid >> 5) & 3) << 5);  // o in [0,128)
    const int jb = (tid >> 7) * 4;                        // float4 k-group base (0 or 4)
    // U generation (vectorized): 32 col-groups(x4) x 8 row-groups(x4)
    const int ucg = (tid & 31) * 4;
    const int urg = (tid >> 5) * 4;
    // compute: 16(o) x 16(col) threads, 8x8 tile each
    const int to = tid >> 4;
    const int tc = tid & 15;
    // output reduction
    const int oo = tid & 127;
    const int ob = tid >> 7;

    const float* Wls[3] = {W0, W1, W2};
    const float* bls[3] = {bias0, bias1, bias2};
    const int    Ks[3]  = {Fd * Fd, HD * Fd, HD * Fd};

    for (int layer = 0; layer < 3; ++layer) {
        const float* Wl = Wls[layer];
        const int K  = Ks[layer];
        const int nk = K / KT;
        // U source: layer 0 multiplies x0 by itself
        const float* hsrc = (layer == 0) ? &sm.x0s[0][0] : &sm.hids[0][0];
        const int hstride  = (layer == 0) ? NCOL : HPAD;

        unsigned long long acc[8][4];
        #pragma unroll
        for (int i = 0; i < 8; ++i)
            #pragma unroll
            for (int j = 0; j < 4; ++j) acc[i][j] = 0ull;

        float4 wreg[4];
        // ---- prologue: stage tile 0 into buffer 0 ----
        __syncthreads();   // x0s ready (layer 0); prior-layer consumers done otherwise
        #pragma unroll
        for (int i = 0; i < 4; ++i)
            wreg[i] = *reinterpret_cast<const float4*>(Wl + (size_t)wo * K + (jb + i) * 4);
        #pragma unroll
        for (int i = 0; i < 4; ++i) {
            int kr = (jb + i) * 4;
            float4 v = wreg[i];
            *reinterpret_cast<float2*>(&sm.Ws2[0][kr + 0][2 * wo]) = make_float2(v.x, v.x);
            *reinterpret_cast<float2*>(&sm.Ws2[0][kr + 1][2 * wo]) = make_float2(v.y, v.y);
            *reinterpret_cast<float2*>(&sm.Ws2[0][kr + 2][2 * wo]) = make_float2(v.z, v.z);
            *reinterpret_cast<float2*>(&sm.Ws2[0][kr + 3][2 * wo]) = make_float2(v.w, v.w);
        }
        {
            float4 hv = *reinterpret_cast<const float4*>(hsrc + (size_t)0 * hstride + ucg);
            #pragma unroll
            for (int r = 0; r < 4; ++r) {
                int m = urg + r;
                float4 xv = *reinterpret_cast<const float4*>(&sm.x0s[m][ucg]);
                *reinterpret_cast<float4*>(&sm.Us[0][m][ucg]) =
                    make_float4(hv.x * xv.x, hv.y * xv.y, hv.z * xv.z, hv.w * xv.w);
            }
        }
        if (nk > 1) {
            const float* base = Wl + (size_t)wo * K + KT;
            #pragma unroll
            for (int i = 0; i < 4; ++i)
                wreg[i] = *reinterpret_cast<const float4*>(base + (jb + i) * 4);
        }
        __syncthreads();

        // ---- main loop: stage tile kt+1 (overlapped) + compute tile kt ----
        for (int kt = 0; kt < nk; ++kt) {
            const int cur = kt & 1;
            const int nxt = cur ^ 1;

            if (kt + 1 < nk) {
                // stage W tile kt+1 (duplicated pairs) from prefetched wreg
                #pragma unroll
                for (int i = 0; i < 4; ++i) {
                    int kr = (jb + i) * 4;
                    float4 v = wreg[i];
                    *reinterpret_cast<float2*>(&sm.Ws2[nxt][kr + 0][2 * wo]) = make_float2(v.x, v.x);
                    *reinterpret_cast<float2*>(&sm.Ws2[nxt][kr + 1][2 * wo]) = make_float2(v.y, v.y);
                    *reinterpret_cast<float2*>(&sm.Ws2[nxt][kr + 2][2 * wo]) = make_float2(v.z, v.z);
                    *reinterpret_cast<float2*>(&sm.Ws2[nxt][kr + 3][2 * wo]) = make_float2(v.w, v.w);
                }
                // stage U tile kt+1: Us[m][col] = hsrc[kt+1][col] * x0s[m][col]
                float4 hv = *reinterpret_cast<const float4*>(hsrc + (size_t)(kt + 1) * hstride + ucg);
                #pragma unroll
                for (int r = 0; r < 4; ++r) {
                    int m = urg + r;
                    float4 xv = *reinterpret_cast<const float4*>(&sm.x0s[m][ucg]);
                    *reinterpret_cast<float4*>(&sm.Us[nxt][m][ucg]) =
                        make_float4(hv.x * xv.x, hv.y * xv.y, hv.z * xv.z, hv.w * xv.w);
                }
            }
            if (kt + 2 < nk) {
                const float* base = Wl + (size_t)wo * K + (size_t)(kt + 2) * KT;
                #pragma unroll
                for (int i = 0; i < 4; ++i)
                    wreg[i] = *reinterpret_cast<const float4*>(base + (jb + i) * 4);
            }

            // compute tile kt from buffer cur: per k, 6 LDS.128 + 32 fma.f32x2
            const float (*Wb)[WPAD] = sm.Ws2[cur];
            const float (*Ub)[UPAD] = sm.Us[cur];
            #pragma unroll 4
            for (int k = 0; k < KT; ++k) {
                ulonglong2 a01 = *reinterpret_cast<const ulonglong2*>(&Wb[k][to * 16 + 0]);
                ulonglong2 a23 = *reinterpret_cast<const ulonglong2*>(&Wb[k][to * 16 + 4]);
                ulonglong2 a45 = *reinterpret_cast<const ulonglong2*>(&Wb[k][to * 16 + 8]);
                ulonglong2 a67 = *reinterpret_cast<const ulonglong2*>(&Wb[k][to * 16 + 12]);
                ulonglong2 c01 = *reinterpret_cast<const ulonglong2*>(&Ub[k][tc * 8 + 0]);
                ulonglong2 c23 = *reinterpret_cast<const ulonglong2*>(&Ub[k][tc * 8 + 4]);
                unsigned long long a[8] = {a01.x, a01.y, a23.x, a23.y,
                                           a45.x, a45.y, a67.x, a67.y};
                unsigned long long c[4] = {c01.x, c01.y, c23.x, c23.y};
                #pragma unroll
                for (int i = 0; i < 8; ++i)
                    #pragma unroll
                    for (int j = 0; j < 4; ++j)
                        acc[i][j] = ffma2(a[i], c[j], acc[i][j]);
            }
            __syncthreads();   // buffer nxt fully staged; buffer cur free for restage
        }

        // ---- epilogue: bias + ReLU -> hids (k-loop fully consumed old hids) ----
        {
            const float* bl = bls[layer];
            float bi[8];
            #pragma unroll
            for (int i = 0; i < 8; ++i) bi[i] = __ldg(&bl[to * 8 + i]);

            #pragma unroll
            for (int i = 0; i < 8; ++i) {
                float r[8];
                #pragma unroll
                for (int j = 0; j < 4; ++j) {
                    float lo, hi;
                    unpack2(acc[i][j], lo, hi);
                    lo += bi[i]; hi += bi[i];
                    r[2 * j]     = fmaxf(lo, 0.0f);
                    r[2 * j + 1] = fmaxf(hi, 0.0f);
                }
                *reinterpret_cast<float4*>(&sm.hids[to * 8 + i][tc * 8 + 0]) =
                    make_float4(r[0], r[1], r[2], r[3]);
                *reinterpret_cast<float4*>(&sm.hids[to * 8 + i][tc * 8 + 4]) =
                    make_float4(r[4], r[5], r[6], r[7]);
            }
        }
        __syncthreads();

        // ---- out[b0+ob, layer*128 + oo] = sum_d hids[oo][ob*64 + d] ----
        {
            float s = 0.0f;
            #pragma unroll
            for (int d4 = 0; d4 < 16; ++d4) {
                float4 v = *reinterpret_cast<const float4*>(&sm.hids[oo][ob * Dd + d4 * 4]);
                s += (v.x + v.y) + (v.z + v.w);
            }
            out[(size_t)(b0 + ob) * OUTW + layer * HD + oo] = s;
        }
        // next layer's prologue __syncthreads orders these reads before buffer reuse.
    }
}

} // namespace

extern "C" void kernel_launch(void* const* d_in, const int* in_sizes, int n_in,
                              void* d_out, int out_size) {
    const float* x  = (const float*)d_in[0];
    const float* W0 = (const float*)d_in[1];
    const float* b0 = (const float*)d_in[2];
    const float* W1 = (const float*)d_in[3];
    const float* b1 = (const float*)d_in[4];
    const float* W2 = (const float*)d_in[5];
    const float* b2 = (const float*)d_in[6];
    float* out = (float*)d_out;

    static_assert(sizeof(Smem) <= 227 * 1024, "smem budget");
    cudaFuncSetAttribute(cin_kernel, cudaFuncAttributeMaxDynamicSharedMemorySize,
                         (int)sizeof(Smem));
    cin_kernel<<<Bt / BT, THREADS, sizeof(Smem)>>>(x, W0, b0, W1, b1, W2, b2, out);
}

// round 8
// speedup vs baseline: 3.8830x; 3.6003x over previous
#include <cuda_runtime.h>
#include <cuda_bf16.h>
#include <cstdint>

// CIN_74603581932155 — bf16 hi/lo split GEMM on warp-level mma.sync (HMMA).
// tcgen05 unavailable (toolchain targets sm_103 w/o 'a' features) -> mma.sync+ldmatrix.
//
// Per batch-pair CTA:  D(128o x 128col) = W(128 x K) * U^T
//   U[k][col] = hid[h][col] * x0[m][col], k = h*32+m, col = bb*64+d
//   K = 1024 / 4096 / 4096.   W = Whi+Wlo (truncation split), U = Uhi+Ulo.
//   D += Whi*Uhi + Whi*Ulo + Wlo*Uhi   (fp32 register accumulators).
// R7 fix: hidT gets its own stride-129 region (R6 reused the 36-float x0T
// stride for h<128 -> SMEM overrun -> illegal address).

namespace {

constexpr int THREADS = 256;
constexpr int NTILE_L0 = 16, NTILE_L12 = 64;
constexpr int NTILES = NTILE_L0 + 2 * NTILE_L12;   // 144
constexpr int WSTR_B = 144;                        // smem row stride bytes (72 bf16)
constexpr int WT_BYTES = 128 * WSTR_B;             // 18432 per (hi|lo) tile
constexpr int XSTR = 36;                           // x0T float stride (m < 32)
constexpr int HSTR = 129;                          // hidT float stride (h < 128)

constexpr int OFF_W    = 0;                          // [buf][hl] 4 x 18432
constexpr int OFF_U    = OFF_W + 4 * WT_BYTES;       // [buf][hl] 4 x 18432
constexpr int OFF_X0T  = OFF_U + 4 * WT_BYTES;       // float x0T[128][36]
constexpr int OFF_HIDT = OFF_X0T + 128 * XSTR * 4;   // float hidT[128][129]
constexpr int SMEM_TOTAL = OFF_HIDT + 128 * HSTR * 4;  // 231936
static_assert(SMEM_TOTAL <= 227 * 1024, "smem budget");

// Pre-split W, flat K-major tile rows: [hl][tile][o*64 + kk] (bf16)
__device__ __align__(16) unsigned char g_Wsplit[2][NTILES][128 * 128];

__device__ __forceinline__ uint32_t smem_u32(const void* p) {
    uint32_t a;
    asm("{ .reg .u64 t; cvta.to.shared.u64 t, %1; cvt.u32.u64 %0, t; }" : "=r"(a) : "l"(p));
    return a;
}

#define CPASYNC16(dst, src) \
    asm volatile("cp.async.ca.shared.global [%0], [%1], 16;" :: "r"(dst), "l"(src) : "memory")

#define LDSM4(r, a) \
    asm volatile("ldmatrix.sync.aligned.m8n8.x4.shared.b16 {%0,%1,%2,%3}, [%4];" \
        : "=r"((r)[0]), "=r"((r)[1]), "=r"((r)[2]), "=r"((r)[3]) : "r"(a))

#define MMA16816(d, a, b) \
    asm volatile("mma.sync.aligned.m16n8k16.row.col.f32.bf16.bf16.f32 " \
        "{%0,%1,%2,%3}, {%4,%5,%6,%7}, {%8,%9}, {%0,%1,%2,%3};" \
        : "+f"((d)[0]), "+f"((d)[1]), "+f"((d)[2]), "+f"((d)[3]) \
        : "r"((a)[0]), "r"((a)[1]), "r"((a)[2]), "r"((a)[3]), "r"((b)[0]), "r"((b)[1]))

// ---------------- prep: split W into bf16 hi/lo tiles -------------------------
__global__ void prep_w_kernel(const float* __restrict__ W0,
                              const float* __restrict__ W1,
                              const float* __restrict__ W2)
{
    int tile = blockIdx.x;              // 0..143
    int tb; const float* Ws; int K;
    if (tile < NTILE_L0)      { tb = tile;            Ws = W0; K = 1024; }
    else if (tile < 80)       { tb = tile - NTILE_L0; Ws = W1; K = 4096; }
    else                      { tb = tile - 80;       Ws = W2; K = 4096; }

    int o = threadIdx.x >> 1;
    int half = threadIdx.x & 1;
    __nv_bfloat16* hi_b = reinterpret_cast<__nv_bfloat16*>(g_Wsplit[0][tile]);
    __nv_bfloat16* lo_b = reinterpret_cast<__nv_bfloat16*>(g_Wsplit[1][tile]);

    #pragma unroll 4
    for (int j = 0; j < 32; ++j) {
        int kk = half * 32 + j;
        float w = Ws[(size_t)o * K + (size_t)tb * 64 + kk];
        uint32_t ub = __float_as_uint(w);
        float hif = __uint_as_float(ub & 0xFFFF0000u);
        float lof = w - hif;
        hi_b[o * 64 + kk] = __ushort_as_bfloat16((unsigned short)(ub >> 16));
        lo_b[o * 64 + kk] = __float2bfloat16_rn(lof);
    }
}

// ---------------- main kernel --------------------------------------------------
__global__ void __launch_bounds__(THREADS, 1)
cin_mma_kernel(const float* __restrict__ x,
               const float* __restrict__ bias0,
               const float* __restrict__ bias1,
               const float* __restrict__ bias2,
               float* __restrict__ out)
{
    extern __shared__ char smem[];
    const uint32_t sb = smem_u32(smem);
    const int tid = threadIdx.x;
    const int wid = tid >> 5;
    const int lane = tid & 31;
    const int b0 = blockIdx.x * 2;

    float* x0T  = reinterpret_cast<float*>(smem + OFF_X0T);
    float* hidT = reinterpret_cast<float*>(smem + OFF_HIDT);

    // ---- build x0T[col][m], col = bb*64 + d ----
    {
        const float* xg = x + (size_t)b0 * 2048;
        #pragma unroll
        for (int r = 0; r < 4; ++r) {
            int idx4 = tid + THREADS * r;           // 0..1023 float4s
            int bb = idx4 >> 9, rem = idx4 & 511;
            int m = rem >> 4, d4 = rem & 15;
            float4 v = *reinterpret_cast<const float4*>(xg + bb * 2048 + m * 64 + d4 * 4);
            int col0 = bb * 64 + d4 * 4;
            x0T[(col0 + 0) * XSTR + m] = v.x;
            x0T[(col0 + 1) * XSTR + m] = v.y;
            x0T[(col0 + 2) * XSTR + m] = v.z;
            x0T[(col0 + 3) * XSTR + m] = v.w;
        }
    }
    __syncthreads();

    // ---- per-warp tile mapping: 4(o) x 2(col) warps, warp tile 32 x 64 ----
    const int ow = wid & 3, cw = wid >> 2;
    const int o_base = ow * 32;
    const int col_base = cw * 64;
    // A (W) ldmatrix: lanes 0-15 rows m0-15 @k0-7, lanes 16-31 same rows @k8-15
    const uint32_t a_off = (uint32_t)(o_base + (lane & 15)) * WSTR_B
                         + (uint32_t)(lane >> 4) * 16;
    // B (U) ldmatrix: n0-7@klo | n0-7@khi | n8-15@klo | n8-15@khi
    const uint32_t b_off = (uint32_t)(col_base + (lane & 7) + ((lane >> 4) << 3)) * WSTR_B
                         + (uint32_t)((lane >> 3) & 1) * 16;

    // U-gen role
    const int ucol = tid >> 1;
    const int uhalf = tid & 1;

    const float* biases[3] = {bias0, bias1, bias2};
    const int nk_l[3] = {NTILE_L0, NTILE_L12, NTILE_L12};
    const int tb_l[3] = {0, NTILE_L0, NTILE_L0 + NTILE_L12};

    for (int layer = 0; layer < 3; ++layer) {
        const int nk = nk_l[layer];
        const float* hsrc = (layer == 0) ? x0T : hidT;
        const int hstr = (layer == 0) ? XSTR : HSTR;

        float acc[2][8][4];
        #pragma unroll
        for (int mi = 0; mi < 2; ++mi)
            #pragma unroll
            for (int nj = 0; nj < 8; ++nj)
                #pragma unroll
                for (int q = 0; q < 4; ++q) acc[mi][nj][q] = 0.0f;

        // ---- staging (cp.async W + in-smem U-gen) ----
        auto stage = [&](int t, int buf) {
            const int tile = tb_l[layer] + t;
            const uint32_t wdst = sb + OFF_W + (uint32_t)buf * 2 * WT_BYTES;
            #pragma unroll
            for (int r = 0; r < 8; ++r) {
                int c = tid + THREADS * r;          // 0..2047 16B chunks
                int hl = c >> 10, rem = c & 1023, row = rem >> 3, seg = rem & 7;
                uint32_t dst = wdst + (uint32_t)hl * WT_BYTES
                             + (uint32_t)row * WSTR_B + (uint32_t)seg * 16;
                CPASYNC16(dst, &g_Wsplit[hl][tile][row * 128 + seg * 16]);
            }
            asm volatile("cp.async.commit_group;" ::: "memory");

            const uint32_t udst = sb + OFF_U + (uint32_t)buf * 2 * WT_BYTES;
            const int h = 2 * t + uhalf;
            const float hv = hsrc[ucol * hstr + h];
            const float* xr = x0T + ucol * XSTR;
            const uint32_t ub = udst + (uint32_t)ucol * WSTR_B + (uint32_t)uhalf * 64;
            #pragma unroll
            for (int i8 = 0; i8 < 32; i8 += 8) {
                float4 xa = *reinterpret_cast<const float4*>(xr + i8);
                float4 xb = *reinterpret_cast<const float4*>(xr + i8 + 4);
                float u[8] = {hv * xa.x, hv * xa.y, hv * xa.z, hv * xa.w,
                              hv * xb.x, hv * xb.y, hv * xb.z, hv * xb.w};
                uint32_t hp[4], lp[4];
                #pragma unroll
                for (int p = 0; p < 4; ++p) {
                    uint32_t u0 = __float_as_uint(u[2 * p]);
                    uint32_t u1 = __float_as_uint(u[2 * p + 1]);
                    hp[p] = __byte_perm(u0, u1, 0x7632);     // {u0.hi16, u1.hi16}
                    float l0 = u[2 * p]     - __uint_as_float(u0 & 0xFFFF0000u);
                    float l1 = u[2 * p + 1] - __uint_as_float(u1 & 0xFFFF0000u);
                    asm("cvt.rn.bf16x2.f32 %0, %2, %1;" : "=r"(lp[p]) : "f"(l0), "f"(l1));
                }
                asm volatile("st.shared.v4.b32 [%0], {%1,%2,%3,%4};"
                             :: "r"(ub + i8 * 2), "r"(hp[0]), "r"(hp[1]), "r"(hp[2]), "r"(hp[3])
                             : "memory");
                asm volatile("st.shared.v4.b32 [%0], {%1,%2,%3,%4};"
                             :: "r"(ub + WT_BYTES + i8 * 2), "r"(lp[0]), "r"(lp[1]), "r"(lp[2]), "r"(lp[3])
                             : "memory");
            }
        };

        // ---- compute one 64-k tile from buffer buf ----
        auto compute = [&](int buf) {
            const uint32_t whi = sb + OFF_W + (uint32_t)buf * 2 * WT_BYTES;
            const uint32_t wlo = whi + WT_BYTES;
            const uint32_t uhi = sb + OFF_U + (uint32_t)buf * 2 * WT_BYTES;
            const uint32_t ulo = uhi + WT_BYTES;
            #pragma unroll
            for (int kk = 0; kk < 4; ++kk) {
                uint32_t ah[2][4], al[2][4], bh[8][2], bl[8][2];
                const uint32_t ka = a_off + kk * 32;
                LDSM4(ah[0], whi + ka);
                LDSM4(ah[1], whi + ka + 16 * WSTR_B);
                LDSM4(al[0], wlo + ka);
                LDSM4(al[1], wlo + ka + 16 * WSTR_B);
                const uint32_t kb = b_off + kk * 32;
                #pragma unroll
                for (int njp = 0; njp < 4; ++njp) {
                    uint32_t t0[4], t1[4];
                    LDSM4(t0, uhi + kb + njp * 16 * WSTR_B);
                    LDSM4(t1, ulo + kb + njp * 16 * WSTR_B);
                    bh[2 * njp][0] = t0[0]; bh[2 * njp][1] = t0[1];
                    bh[2 * njp + 1][0] = t0[2]; bh[2 * njp + 1][1] = t0[3];
                    bl[2 * njp][0] = t1[0]; bl[2 * njp][1] = t1[1];
                    bl[2 * njp + 1][0] = t1[2]; bl[2 * njp + 1][1] = t1[3];
                }
                #pragma unroll
                for (int mi = 0; mi < 2; ++mi)
                    #pragma unroll
                    for (int nj = 0; nj < 8; ++nj)
                        MMA16816(acc[mi][nj], ah[mi], bh[nj]);
                #pragma unroll
                for (int mi = 0; mi < 2; ++mi)
                    #pragma unroll
                    for (int nj = 0; nj < 8; ++nj)
                        MMA16816(acc[mi][nj], ah[mi], bl[nj]);
                #pragma unroll
                for (int mi = 0; mi < 2; ++mi)
                    #pragma unroll
                    for (int nj = 0; nj < 8; ++nj)
                        MMA16816(acc[mi][nj], al[mi], bh[nj]);
            }
        };

        stage(0, 0);
        for (int kt = 0; kt < nk; ++kt) {
            const int cur = kt & 1;
            if (kt + 1 < nk) {
                stage(kt + 1, cur ^ 1);
                asm volatile("cp.async.wait_group 1;" ::: "memory");
            } else {
                asm volatile("cp.async.wait_group 0;" ::: "memory");
            }
            __syncthreads();      // buf cur fully staged & visible
            compute(cur);
            __syncthreads();      // buf cur consumed -> restageable next iter
        }

        // ---- epilogue: bias + ReLU, hidT[col][h] store, d-sum -> out ----
        {
            const float* bl = biases[layer];
            #pragma unroll
            for (int mi = 0; mi < 2; ++mi) {
                #pragma unroll
                for (int s = 0; s < 2; ++s) {
                    const int h = o_base + mi * 16 + (lane >> 2) + 8 * s;
                    const float bv = __ldg(&bl[h]);
                    float rs = 0.0f;
                    #pragma unroll
                    for (int nj = 0; nj < 8; ++nj) {
                        float z0 = fmaxf(acc[mi][nj][2 * s] + bv, 0.0f);
                        float z1 = fmaxf(acc[mi][nj][2 * s + 1] + bv, 0.0f);
                        rs += z0 + z1;
                        if (layer < 2) {
                            int c0 = col_base + nj * 8 + (lane & 3) * 2;
                            hidT[c0 * HSTR + h] = z0;
                            hidT[(c0 + 1) * HSTR + h] = z1;
                        }
                    }
                    rs += __shfl_xor_sync(0xFFFFFFFFu, rs, 1);
                    rs += __shfl_xor_sync(0xFFFFFFFFu, rs, 2);
                    if ((lane & 3) == 0)
                        out[(size_t)(b0 + cw) * 384 + layer * 128 + h] = rs;
                }
            }
        }
        __syncthreads();   // hidT complete before next layer's U-gen / restage
    }
}

} // namespace

extern "C" void kernel_launch(void* const* d_in, const int* in_sizes, int n_in,
                              void* d_out, int out_size) {
    const float* x  = (const float*)d_in[0];
    const float* W0 = (const float*)d_in[1];
    const float* b0 = (const float*)d_in[2];
    const float* W1 = (const float*)d_in[3];
    const float* b1 = (const float*)d_in[4];
    const float* W2 = (const float*)d_in[5];
    const float* b2 = (const float*)d_in[6];
    float* out = (float*)d_out;

    prep_w_kernel<<<NTILES, THREADS>>>(W0, W1, W2);

    cudaFuncSetAttribute(cin_mma_kernel, cudaFuncAttributeMaxDynamicSharedMemorySize,
                         SMEM_TOTAL);
    cin_mma_kernel<<<512, THREADS, SMEM_TOTAL>>>(x, b0, b1, b2, out);
}

// round 9
// speedup vs baseline: 3.9879x; 1.0270x over previous
#include <cuda_runtime.h>
#include <cuda_bf16.h>
#include <cstdint>

// CIN_74603581932155 — bf16 hi/lo split GEMM on warp-level mma.sync (HMMA).
// R8: staging (cp.async W + U-gen) fused INTO the compute stream — U-gen for
// tile kt+1 is interleaved between the kk-blocks of tile kt's MMAs, and the
// per-tile barrier count drops from 2 to 1. Tensor pipe no longer idles
// through a serialized staging phase.
//
// Per batch-pair CTA:  D(128o x 128col) = W(128 x K) * U^T
//   U[k][col] = hid[h][col] * x0[m][col], k = h*32+m, col = bb*64+d
//   K = 1024 / 4096 / 4096.   W = Whi+Wlo (truncation split), U = Uhi+Ulo.
//   D += Whi*Uhi + Whi*Ulo + Wlo*Uhi   (fp32 register accumulators).

namespace {

constexpr int THREADS = 256;
constexpr int NTILE_L0 = 16, NTILE_L12 = 64;
constexpr int NTILES = NTILE_L0 + 2 * NTILE_L12;   // 144
constexpr int WSTR_B = 144;                        // smem row stride bytes (72 bf16)
constexpr int WT_BYTES = 128 * WSTR_B;             // 18432 per (hi|lo) tile
constexpr int XSTR = 36;                           // x0T float stride (m < 32)
constexpr int HSTR = 129;                          // hidT float stride (h < 128)

constexpr int OFF_W    = 0;                          // [buf][hl] 4 x 18432
constexpr int OFF_U    = OFF_W + 4 * WT_BYTES;       // [buf][hl] 4 x 18432
constexpr int OFF_X0T  = OFF_U + 4 * WT_BYTES;       // float x0T[128][36]
constexpr int OFF_HIDT = OFF_X0T + 128 * XSTR * 4;   // float hidT[128][129]
constexpr int SMEM_TOTAL = OFF_HIDT + 128 * HSTR * 4;  // 231936
static_assert(SMEM_TOTAL <= 227 * 1024, "smem budget");

// Pre-split W, flat K-major tile rows: [hl][tile][o*64 + kk] (bf16)
__device__ __align__(16) unsigned char g_Wsplit[2][NTILES][128 * 128];

__device__ __forceinline__ uint32_t smem_u32(const void* p) {
    uint32_t a;
    asm("{ .reg .u64 t; cvta.to.shared.u64 t, %1; cvt.u32.u64 %0, t; }" : "=r"(a) : "l"(p));
    return a;
}

#define CPASYNC16(dst, src) \
    asm volatile("cp.async.ca.shared.global [%0], [%1], 16;" :: "r"(dst), "l"(src) : "memory")

#define LDSM4(r, a) \
    asm volatile("ldmatrix.sync.aligned.m8n8.x4.shared.b16 {%0,%1,%2,%3}, [%4];" \
        : "=r"((r)[0]), "=r"((r)[1]), "=r"((r)[2]), "=r"((r)[3]) : "r"(a))

#define MMA16816(d, a, b) \
    asm volatile("mma.sync.aligned.m16n8k16.row.col.f32.bf16.bf16.f32 " \
        "{%0,%1,%2,%3}, {%4,%5,%6,%7}, {%8,%9}, {%0,%1,%2,%3};" \
        : "+f"((d)[0]), "+f"((d)[1]), "+f"((d)[2]), "+f"((d)[3]) \
        : "r"((a)[0]), "r"((a)[1]), "r"((a)[2]), "r"((a)[3]), "r"((b)[0]), "r"((b)[1]))

// ---------------- prep: split W into bf16 hi/lo tiles -------------------------
__global__ void prep_w_kernel(const float* __restrict__ W0,
                              const float* __restrict__ W1,
                              const float* __restrict__ W2)
{
    int tile = blockIdx.x;              // 0..143
    int tb; const float* Ws; int K;
    if (tile < NTILE_L0)      { tb = tile;            Ws = W0; K = 1024; }
    else if (tile < 80)       { tb = tile - NTILE_L0; Ws = W1; K = 4096; }
    else                      { tb = tile - 80;       Ws = W2; K = 4096; }

    int o = threadIdx.x >> 1;
    int half = threadIdx.x & 1;
    __nv_bfloat16* hi_b = reinterpret_cast<__nv_bfloat16*>(g_Wsplit[0][tile]);
    __nv_bfloat16* lo_b = reinterpret_cast<__nv_bfloat16*>(g_Wsplit[1][tile]);

    #pragma unroll 4
    for (int j = 0; j < 32; ++j) {
        int kk = half * 32 + j;
        float w = Ws[(size_t)o * K + (size_t)tb * 64 + kk];
        uint32_t ub = __float_as_uint(w);
        float hif = __uint_as_float(ub & 0xFFFF0000u);
        float lof = w - hif;
        hi_b[o * 64 + kk] = __ushort_as_bfloat16((unsigned short)(ub >> 16));
        lo_b[o * 64 + kk] = __float2bfloat16_rn(lof);
    }
}

// ---------------- main kernel --------------------------------------------------
__global__ void __launch_bounds__(THREADS, 1)
cin_mma_kernel(const float* __restrict__ x,
               const float* __restrict__ bias0,
               const float* __restrict__ bias1,
               const float* __restrict__ bias2,
               float* __restrict__ out)
{
    extern __shared__ char smem[];
    const uint32_t sb = smem_u32(smem);
    const int tid = threadIdx.x;
    const int wid = tid >> 5;
    const int lane = tid & 31;
    const int b0 = blockIdx.x * 2;

    float* x0T  = reinterpret_cast<float*>(smem + OFF_X0T);
    float* hidT = reinterpret_cast<float*>(smem + OFF_HIDT);

    // ---- build x0T[col][m], col = bb*64 + d ----
    {
        const float* xg = x + (size_t)b0 * 2048;
        #pragma unroll
        for (int r = 0; r < 4; ++r) {
            int idx4 = tid + THREADS * r;           // 0..1023 float4s
            int bb = idx4 >> 9, rem = idx4 & 511;
            int m = rem >> 4, d4 = rem & 15;
            float4 v = *reinterpret_cast<const float4*>(xg + bb * 2048 + m * 64 + d4 * 4);
            int col0 = bb * 64 + d4 * 4;
            x0T[(col0 + 0) * XSTR + m] = v.x;
            x0T[(col0 + 1) * XSTR + m] = v.y;
            x0T[(col0 + 2) * XSTR + m] = v.z;
            x0T[(col0 + 3) * XSTR + m] = v.w;
        }
    }
    __syncthreads();

    // ---- per-warp tile mapping: 4(o) x 2(col) warps, warp tile 32 x 64 ----
    const int ow = wid & 3, cw = wid >> 2;
    const int o_base = ow * 32;
    const int col_base = cw * 64;
    const uint32_t a_off = (uint32_t)(o_base + (lane & 15)) * WSTR_B
                         + (uint32_t)(lane >> 4) * 16;
    const uint32_t b_off = (uint32_t)(col_base + (lane & 7) + ((lane >> 4) << 3)) * WSTR_B
                         + (uint32_t)((lane >> 3) & 1) * 16;

    // U-gen role
    const int ucol = tid >> 1;
    const int uhalf = tid & 1;
    const float* xr = x0T + ucol * XSTR;

    const float* biases[3] = {bias0, bias1, bias2};
    const int nk_l[3] = {NTILE_L0, NTILE_L12, NTILE_L12};
    const int tb_l[3] = {0, NTILE_L0, NTILE_L0 + NTILE_L12};

    for (int layer = 0; layer < 3; ++layer) {
        const int nk = nk_l[layer];
        const float* hsrc = (layer == 0) ? x0T : hidT;
        const int hstr = (layer == 0) ? XSTR : HSTR;

        float acc[2][8][4];
        #pragma unroll
        for (int mi = 0; mi < 2; ++mi)
            #pragma unroll
            for (int nj = 0; nj < 8; ++nj)
                #pragma unroll
                for (int q = 0; q < 4; ++q) acc[mi][nj][q] = 0.0f;

        // ---- W cp.async issue for tile t into buf ----
        auto w_issue = [&](int t, int buf) {
            const int tile = tb_l[layer] + t;
            const uint32_t wdst = sb + OFF_W + (uint32_t)buf * 2 * WT_BYTES;
            #pragma unroll
            for (int r = 0; r < 8; ++r) {
                int c = tid + THREADS * r;          // 0..2047 16B chunks
                int hl = c >> 10, rem = c & 1023, row = rem >> 3, seg = rem & 7;
                uint32_t dst = wdst + (uint32_t)hl * WT_BYTES
                             + (uint32_t)row * WSTR_B + (uint32_t)seg * 16;
                CPASYNC16(dst, &g_Wsplit[hl][tile][row * 128 + seg * 16]);
            }
            asm volatile("cp.async.commit_group;" ::: "memory");
        };

        // ---- U-gen: one 8-value chunk of tile t into buf ----
        auto ugen_chunk = [&](float hv, int buf, int chunk) {
            const uint32_t udst = sb + OFF_U + (uint32_t)buf * 2 * WT_BYTES;
            const uint32_t ub = udst + (uint32_t)ucol * WSTR_B + (uint32_t)uhalf * 64;
            const int i8 = chunk * 8;
            float4 xa = *reinterpret_cast<const float4*>(xr + i8);
            float4 xb = *reinterpret_cast<const float4*>(xr + i8 + 4);
            float u[8] = {hv * xa.x, hv * xa.y, hv * xa.z, hv * xa.w,
                          hv * xb.x, hv * xb.y, hv * xb.z, hv * xb.w};
            uint32_t hp[4], lp[4];
            #pragma unroll
            for (int p = 0; p < 4; ++p) {
                uint32_t u0 = __float_as_uint(u[2 * p]);
                uint32_t u1 = __float_as_uint(u[2 * p + 1]);
                hp[p] = __byte_perm(u0, u1, 0x7632);     // {u0.hi16, u1.hi16}
                float l0 = u[2 * p]     - __uint_as_float(u0 & 0xFFFF0000u);
                float l1 = u[2 * p + 1] - __uint_as_float(u1 & 0xFFFF0000u);
                asm("cvt.rn.bf16x2.f32 %0, %2, %1;" : "=r"(lp[p]) : "f"(l0), "f"(l1));
            }
            asm volatile("st.shared.v4.b32 [%0], {%1,%2,%3,%4};"
                         :: "r"(ub + i8 * 2), "r"(hp[0]), "r"(hp[1]), "r"(hp[2]), "r"(hp[3])
                         : "memory");
            asm volatile("st.shared.v4.b32 [%0], {%1,%2,%3,%4};"
                         :: "r"(ub + WT_BYTES + i8 * 2), "r"(lp[0]), "r"(lp[1]), "r"(lp[2]), "r"(lp[3])
                         : "memory");
        };

        // ---- prologue: stage tile 0 into buf 0 ----
        w_issue(0, 0);
        {
            const float hv0 = hsrc[ucol * hstr + uhalf];
            #pragma unroll
            for (int c = 0; c < 4; ++c) ugen_chunk(hv0, 0, c);
        }
        asm volatile("cp.async.wait_group 0;" ::: "memory");
        __syncthreads();

        // ---- main loop: compute(cur) with staging of kt+1 interleaved ----
        for (int kt = 0; kt < nk; ++kt) {
            const int cur = kt & 1;
            const int nxt = cur ^ 1;
            const bool more = (kt + 1 < nk);

            float hv = 0.0f;
            if (more) {
                w_issue(kt + 1, nxt);
                asm volatile("cp.async.wait_group 1;" ::: "memory");
                hv = hsrc[ucol * hstr + (2 * (kt + 1) + uhalf)];
            } else {
                asm volatile("cp.async.wait_group 0;" ::: "memory");
            }

            const uint32_t whi = sb + OFF_W + (uint32_t)cur * 2 * WT_BYTES;
            const uint32_t wlo = whi + WT_BYTES;
            const uint32_t uhi = sb + OFF_U + (uint32_t)cur * 2 * WT_BYTES;
            const uint32_t ulo = uhi + WT_BYTES;

            #pragma unroll
            for (int kk = 0; kk < 4; ++kk) {
                // interleave 1/4 of next tile's U-gen ahead of this kk-block;
                // writes go to buf nxt, reads below come from buf cur.
                if (more) ugen_chunk(hv, nxt, kk);

                uint32_t ah[2][4], al[2][4], bh[8][2], bl[8][2];
                const uint32_t ka = a_off + kk * 32;
                LDSM4(ah[0], whi + ka);
                LDSM4(ah[1], whi + ka + 16 * WSTR_B);
                LDSM4(al[0], wlo + ka);
                LDSM4(al[1], wlo + ka + 16 * WSTR_B);
                const uint32_t kb = b_off + kk * 32;
                #pragma unroll
                for (int njp = 0; njp < 4; ++njp) {
                    uint32_t t0[4], t1[4];
                    LDSM4(t0, uhi + kb + njp * 16 * WSTR_B);
                    LDSM4(t1, ulo + kb + njp * 16 * WSTR_B);
                    bh[2 * njp][0] = t0[0]; bh[2 * njp][1] = t0[1];
                    bh[2 * njp + 1][0] = t0[2]; bh[2 * njp + 1][1] = t0[3];
                    bl[2 * njp][0] = t1[0]; bl[2 * njp][1] = t1[1];
                    bl[2 * njp + 1][0] = t1[2]; bl[2 * njp + 1][1] = t1[3];
                }
                #pragma unroll
                for (int mi = 0; mi < 2; ++mi)
                    #pragma unroll
                    for (int nj = 0; nj < 8; ++nj)
                        MMA16816(acc[mi][nj], ah[mi], bh[nj]);
                #pragma unroll
                for (int mi = 0; mi < 2; ++mi)
                    #pragma unroll
                    for (int nj = 0; nj < 8; ++nj)
                        MMA16816(acc[mi][nj], ah[mi], bl[nj]);
                #pragma unroll
                for (int mi = 0; mi < 2; ++mi)
                    #pragma unroll
                    for (int nj = 0; nj < 8; ++nj)
                        MMA16816(acc[mi][nj], al[mi], bh[nj]);
            }
            // single barrier: nxt fully staged by all warps AND cur fully
            // consumed (next iteration computes nxt, restages into cur).
            __syncthreads();
        }

        // ---- epilogue: bias + ReLU, hidT[col][h] store, d-sum -> out ----
        {
            const float* bl = biases[layer];
            #pragma unroll
            for (int mi = 0; mi < 2; ++mi) {
                #pragma unroll
                for (int s = 0; s < 2; ++s) {
                    const int h = o_base + mi * 16 + (lane >> 2) + 8 * s;
                    const float bv = __ldg(&bl[h]);
                    float rs = 0.0f;
                    #pragma unroll
                    for (int nj = 0; nj < 8; ++nj) {
                        float z0 = fmaxf(acc[mi][nj][2 * s] + bv, 0.0f);
                        float z1 = fmaxf(acc[mi][nj][2 * s + 1] + bv, 0.0f);
                        rs += z0 + z1;
                        if (layer < 2) {
                            int c0 = col_base + nj * 8 + (lane & 3) * 2;
                            hidT[c0 * HSTR + h] = z0;
                            hidT[(c0 + 1) * HSTR + h] = z1;
                        }
                    }
                    rs += __shfl_xor_sync(0xFFFFFFFFu, rs, 1);
                    rs += __shfl_xor_sync(0xFFFFFFFFu, rs, 2);
                    if ((lane & 3) == 0)
                        out[(size_t)(b0 + cw) * 384 + layer * 128 + h] = rs;
                }
            }
        }
        __syncthreads();   // hidT complete before next layer's U-gen
    }
}

} // namespace

extern "C" void kernel_launch(void* const* d_in, const int* in_sizes, int n_in,
                              void* d_out, int out_size) {
    const float* x  = (const float*)d_in[0];
    const float* W0 = (const float*)d_in[1];
    const float* b0 = (const float*)d_in[2];
    const float* W1 = (const float*)d_in[3];
    const float* b1 = (const float*)d_in[4];
    const float* W2 = (const float*)d_in[5];
    const float* b2 = (const float*)d_in[6];
    float* out = (float*)d_out;

    prep_w_kernel<<<NTILES, THREADS>>>(W0, W1, W2);

    cudaFuncSetAttribute(cin_mma_kernel, cudaFuncAttributeMaxDynamicSharedMemorySize,
                         SMEM_TOTAL);
    cin_mma_kernel<<<512, THREADS, SMEM_TOTAL>>>(x, b0, b1, b2, out);
}